// round 2
// baseline (speedup 1.0000x reference)
#include <cuda_runtime.h>

#define S_LEN 512
#define BATCH 512
#define HD    128            // H*d
#define NB    4              // batch rows per block
#define NTHR  256            // two groups of 128: W-group / U-group
#define EPSF  1e-15f
#define PEF   1e-5f          // PROJ_EPS

// ---------------- packed f32x2 helpers ----------------
__device__ __forceinline__ unsigned long long pack2f(float lo, float hi) {
    unsigned long long r;
    asm("mov.b64 %0, {%1, %2};" : "=l"(r) : "r"(__float_as_uint(lo)), "r"(__float_as_uint(hi)));
    return r;
}
__device__ __forceinline__ unsigned long long pack_dup(float v) {
    unsigned long long r;
    unsigned u = __float_as_uint(v);
    asm("mov.b64 %0, {%1, %1};" : "=l"(r) : "r"(u));
    return r;
}
__device__ __forceinline__ void unpack2f(unsigned long long p, float &lo, float &hi) {
    unsigned a, b;
    asm("mov.b64 {%0, %1}, %2;" : "=r"(a), "=r"(b) : "l"(p));
    lo = __uint_as_float(a);
    hi = __uint_as_float(b);
}
__device__ __forceinline__ unsigned long long fma2(unsigned long long a,
                                                   unsigned long long b,
                                                   unsigned long long c) {
    unsigned long long d;
    asm("fma.rn.f32x2 %0, %1, %2, %3;" : "=l"(d) : "l"(a), "l"(b), "l"(c));
    return d;
}

// ---------------- Mobius math (per head = 2 elems, partner via shfl.xor 1) ----
__device__ __forceinline__ void project2(float &a, float &b) {
    float n2 = fmaf(a, a, b * b);
    float sc = (1.0f - PEF) * __fdividef(1.0f, fmaxf(n2, 1.0f - PEF));
    a *= sc;
    b *= sc;
}

// project own component; return projected value, set ||proj_head + EPS||
__device__ __forceinline__ float stage_proj(float v, float &norm_out) {
    float q  = __shfl_xor_sync(0xffffffffu, v, 1);
    float n2 = fmaf(v, v, q * q);
    float sc = (1.0f - PEF) * __fdividef(1.0f, fmaxf(n2, 1.0f - PEF));
    float p  = v * sc;
    float pq = q * sc;
    float a0 = p + EPSF, a1 = pq + EPSF;
    norm_out = __fsqrt_rn(fmaf(a0, a0, a1 * a1));
    return p;
}

// mob_mat_mul epilogue. m = own accumulator component, xn = input-head norm.
__device__ __forceinline__ void mmm_post(float m, float xn, float &o0, float &o1) {
    float mp   = __shfl_xor_sync(0xffffffffu, m, 1);
    float a0   = m + EPSF, a1 = mp + EPSF;
    float n2m  = fmaf(a0, a0, a1 * a1);
    float invm = rsqrtf(n2m);
    float Mxn  = n2m * invm;                                        // ||Mx+EPS||
    float r    = __fdividef(Mxn, xn);
    float at   = 0.5f * __logf(__fdividef(1.0f + xn, 1.0f - xn));   // atanh(xn)
    float z    = r * at;
    float e2   = __expf(2.0f * z);
    float t    = 1.0f - __fdividef(2.0f, e2 + 1.0f);                // tanh(z)
    float sc   = t * invm;
    o0 = sc * m;
    o1 = sc * mp;
    project2(o0, o1);
}

__device__ __forceinline__ void mob_add2(float u0, float u1, float v0, float v1,
                                         float &o0, float &o1) {
    v0 += EPSF; v1 += EPSF;
    float nuv = 2.0f * fmaf(u0, v0, u1 * v1);
    float nu  = fmaf(u0, u0, u1 * u1);
    float nv  = fmaf(v0, v0, v1 * v1);
    float idn = __fdividef(1.0f, 1.0f + nuv + nv * nu);
    float cA  = (1.0f + nuv + nv) * idn;
    float cB  = (1.0f - nu) * idn;
    o0 = cA * u0 + cB * v0;
    o1 = cA * u1 + cB * v1;
    project2(o0, o1);
}

// full per-row epilogue: h_new_own = mob_add(mob_add(Wh, Ux), b)
__device__ __forceinline__ float step_row(float wm, float hn, float um, float xn,
                                          float bia, float bip) {
    float w0, w1, u0, u1, s0, s1, o0, o1;
    mmm_post(wm, hn, w0, w1);
    mmm_post(um, xn, u0, u1);
    mob_add2(w0, w1, u0, u1, s0, s1);
    mob_add2(s0, s1, bia, bip, o0, o1);
    return o0;
}

// ---------------- kernel ----------------
// Block: 256 threads. Group0 (tid<128): W column in regs, rows 0,1.
//        Group1: U column in regs, rows 2,3.
// Staging smem: hsp[k] = {pack(h0,h1), pack(h2,h3)}, xsp likewise.
__global__ void __launch_bounds__(NTHR, 1)
hyper_rnn_kernel(const float *__restrict__ xg,   // [B,S,HD]
                 const float *__restrict__ wg,   // [HD,HD] (k, e)
                 const float *__restrict__ ug,
                 const float *__restrict__ bg,   // [HD]
                 float *__restrict__ yg)         // [B,S,HD]
{
    __shared__ ulonglong2 hsp[HD];
    __shared__ ulonglong2 xsp[HD];
    __shared__ unsigned long long other_sm[2 * HD]; // [0]:Uacc01 for grp0, [1]:Wacc23 for grp1

    const int tid = threadIdx.x;
    const bool isW = (tid < HD);
    const int e   = tid & (HD - 1);
    const int b0  = blockIdx.x * NB;
    const int ra  = isW ? 0 : 2;       // first row this group owns
    // own weight column -> registers
    const float *mat = isW ? wg : ug;
    float col[HD];
#pragma unroll
    for (int k = 0; k < HD; ++k) col[k] = mat[k * HD + e];

    float bia = bg[e];
    float bip = __shfl_xor_sync(0xffffffffu, bia, 1);

    // state (this group's two rows), input prefetch
    float ha = 0.0f, hb = 0.0f;
    float xa = xg[((size_t)(b0 + ra) * S_LEN + 0) * HD + e];
    float xb = xg[((size_t)(b0 + ra + 1) * S_LEN + 0) * HD + e];

    const ulonglong2 *src = isW ? hsp : xsp;
    unsigned long long *hslot = ((unsigned long long *)hsp) + 2 * e + (isW ? 0 : 1);
    unsigned long long *xslot = ((unsigned long long *)xsp) + 2 * e + (isW ? 0 : 1);

    for (int s = 0; s < S_LEN; ++s) {
        // ---- staging: project h and x (2 rows each), write packed pairs ----
        float hna, hnb, xna, xnb;
        float hpa = stage_proj(ha, hna);
        float hpb = stage_proj(hb, hnb);
        float xpa = stage_proj(xa, xna);
        float xpb = stage_proj(xb, xnb);
        *hslot = pack2f(hpa, hpb);
        *xslot = pack2f(xpa, xpb);
        __syncthreads();

        // prefetch next step's inputs (hides LDG under matvec)
        if (s + 1 < S_LEN) {
            xa = xg[((size_t)(b0 + ra) * S_LEN + (s + 1)) * HD + e];
            xb = xg[((size_t)(b0 + ra + 1) * S_LEN + (s + 1)) * HD + e];
        }

        // ---- matvec: own matrix x all 4 rows, packed f32x2 ----
        unsigned long long accA = 0ull, accB = 0ull; // rows01 / rows23
#pragma unroll
        for (int k = 0; k < HD; ++k) {
            ulonglong2 hv = src[k];                  // LDS.128 broadcast
            unsigned long long wp = pack_dup(col[k]);
            accA = fma2(wp, hv.x, accA);
            accB = fma2(wp, hv.y, accB);
        }
        // exchange the pair belonging to the other group's rows
        if (isW) other_sm[HD + e] = accB;            // Wh rows 2,3 -> group1
        else     other_sm[e]      = accA;            // Ux rows 0,1 -> group0
        __syncthreads();

        // ---- epilogue for own two rows ----
        unsigned long long wP, uP;
        if (isW) { wP = accA; uP = other_sm[e]; }
        else     { wP = other_sm[HD + e]; uP = accB; }
        float wA, wB, uA, uB;
        unpack2f(wP, wA, wB);
        unpack2f(uP, uA, uB);

        float oa = step_row(wA, hna, uA, xna, bia, bip);
        float ob = step_row(wB, hnb, uB, xnb, bia, bip);

        yg[((size_t)(b0 + ra)     * S_LEN + s) * HD + e] = oa;
        yg[((size_t)(b0 + ra + 1) * S_LEN + s) * HD + e] = ob;
        ha = oa;
        hb = ob;
        // next staging writes hsp/xsp only after this sync-pair cycle:
        // epilogue reads other_sm; next overwrite of other_sm happens after
        // the next __syncthreads() (staging), so ordering is safe.
    }
}

extern "C" void kernel_launch(void *const *d_in, const int *in_sizes, int n_in,
                              void *d_out, int out_size) {
    const float *xg = (const float *)d_in[0];   // inputs [512,512,64,2]
    const float *wg = (const float *)d_in[1];   // w [64,2,64,2] -> [128,128]
    const float *ug = (const float *)d_in[2];   // u
    const float *bg = (const float *)d_in[3];   // b [64,2]
    float *yg = (float *)d_out;

    hyper_rnn_kernel<<<BATCH / NB, NTHR>>>(xg, wg, ug, bg, yg);
}

// round 5
// speedup vs baseline: 1.5726x; 1.5726x over previous
#include <cuda_runtime.h>

#define S_LEN 512
#define BATCH 512
#define HD    128            // H*d
#define NB    4              // batch rows per block
#define NTHR  256            // 2 k-groups x 128 outputs
#define KHALF 64             // k-slices per group
#define EPSF  1e-15f
#define PEF   1e-5f          // PROJ_EPS

// ---------------- packed f32x2 helpers ----------------
__device__ __forceinline__ unsigned long long pack2f(float lo, float hi) {
    unsigned long long r;
    asm("mov.b64 %0, {%1, %2};" : "=l"(r) : "r"(__float_as_uint(lo)), "r"(__float_as_uint(hi)));
    return r;
}
__device__ __forceinline__ void unpack2f(unsigned long long p, float &lo, float &hi) {
    unsigned a, b;
    asm("mov.b64 {%0, %1}, %2;" : "=r"(a), "=r"(b) : "l"(p));
    lo = __uint_as_float(a);
    hi = __uint_as_float(b);
}
__device__ __forceinline__ unsigned long long fma2(unsigned long long a,
                                                   unsigned long long b,
                                                   unsigned long long c) {
    unsigned long long d;
    asm("fma.rn.f32x2 %0, %1, %2, %3;" : "=l"(d) : "l"(a), "l"(b), "l"(c));
    return d;
}
__device__ __forceinline__ unsigned long long add2(unsigned long long a,
                                                   unsigned long long b) {
    unsigned long long d;
    asm("add.rn.f32x2 %0, %1, %2;" : "=l"(d) : "l"(a), "l"(b));
    return d;
}

// ---------------- Mobius math (head = 2 elems, partner via shfl.xor 1) -------
__device__ __forceinline__ void project2(float &a, float &b) {
    float n2 = fmaf(a, a, b * b);
    float sc = (1.0f - PEF) * __fdividef(1.0f, fmaxf(n2, 1.0f - PEF));
    a *= sc;
    b *= sc;
}

// project own component; return projected value, set ||proj_head + EPS||
__device__ __forceinline__ float stage_proj(float v, float &norm_out) {
    float q  = __shfl_xor_sync(0xffffffffu, v, 1);
    float n2 = fmaf(v, v, q * q);
    float sc = (1.0f - PEF) * __fdividef(1.0f, fmaxf(n2, 1.0f - PEF));
    float p  = v * sc;
    float pq = q * sc;
    float a0 = p + EPSF, a1 = pq + EPSF;
    norm_out = __fsqrt_rn(fmaf(a0, a0, a1 * a1));
    return p;
}

// mob_mat_mul epilogue. m = own accumulator component, xn = input-head norm.
__device__ __forceinline__ void mmm_post(float m, float xn, float &o0, float &o1) {
    float mp   = __shfl_xor_sync(0xffffffffu, m, 1);
    float a0   = m + EPSF, a1 = mp + EPSF;
    float n2m  = fmaf(a0, a0, a1 * a1);
    float invm = rsqrtf(n2m);
    float Mxn  = n2m * invm;                                        // ||Mx+EPS||
    float r    = __fdividef(Mxn, xn);
    float at   = 0.5f * __logf(__fdividef(1.0f + xn, 1.0f - xn));   // atanh(xn)
    float z    = r * at;
    float e2   = __expf(2.0f * z);
    float t    = 1.0f - __fdividef(2.0f, e2 + 1.0f);                // tanh(z)
    float sc   = t * invm;
    o0 = sc * m;
    o1 = sc * mp;
    project2(o0, o1);
}

__device__ __forceinline__ void mob_add2(float u0, float u1, float v0, float v1,
                                         float &o0, float &o1) {
    v0 += EPSF; v1 += EPSF;
    float nuv = 2.0f * fmaf(u0, v0, u1 * v1);
    float nu  = fmaf(u0, u0, u1 * u1);
    float nv  = fmaf(v0, v0, v1 * v1);
    float idn = __fdividef(1.0f, 1.0f + nuv + nv * nu);
    float cA  = (1.0f + nuv + nv) * idn;
    float cB  = (1.0f - nu) * idn;
    o0 = cA * u0 + cB * v0;
    o1 = cA * u1 + cB * v1;
    project2(o0, o1);
}

// full per-row epilogue: h_new_own = mob_add(mob_add(Wh, Ux), b)
__device__ __forceinline__ float step_row(float wm, float hn, float um, float xn,
                                          float bia, float bip) {
    float w0, w1, u0, u1, s0, s1, o0, o1;
    mmm_post(wm, hn, w0, w1);
    mmm_post(um, xn, u0, u1);
    mob_add2(w0, w1, u0, u1, s0, s1);
    mob_add2(s0, s1, bia, bip, o0, o1);
    return o0;
}

// ---------------- kernel ----------------
// 256 threads: g = tid>>7 (k-group), e = tid&127 (output column).
// Thread (g,e):
//   - holds packed weights {W[k][e],U[k][e]} for k in [64g, 64g+64) (regs)
//   - owns state rows 2g, 2g+1: staging (projection+norms) and epilogue
//   - matvec partial over its k-range for ALL 4 rows, packed {wacc,uacc}
//   - keeps own rowpair's partial in regs, exchanges only the other rowpair
// Staged smem: s01[k] = {h0,x0,h1,x1} (projected), s23[k] = {h2,x2,h3,x3}.
__global__ void __launch_bounds__(NTHR, 1)
hyper_rnn_kernel(const float *__restrict__ xg,   // [B,S,HD]
                 const float *__restrict__ wg,   // [HD,HD] (k, e)
                 const float *__restrict__ ug,
                 const float *__restrict__ bg,   // [HD]
                 float *__restrict__ yg)         // [B,S,HD]
{
    __shared__ ulonglong2 s01[HD];
    __shared__ ulonglong2 s23[HD];
    __shared__ ulonglong2 psum[2][HD];      // [srcgroup][e] = partial for rowpair 1-srcgroup

    const int tid = threadIdx.x;
    const int g   = tid >> 7;
    const int e   = tid & (HD - 1);
    const int b0  = blockIdx.x * NB;
    const int r0  = 2 * g;            // first owned row

    // packed {W,U} weight column slice -> registers (one-time)
    unsigned long long wu[KHALF];
#pragma unroll
    for (int j = 0; j < KHALF; ++j) {
        int k = g * KHALF + j;
        wu[j] = pack2f(wg[k * HD + e], ug[k * HD + e]);
    }

    float bia = bg[e];
    float bip = __shfl_xor_sync(0xffffffffu, bia, 1);

    float ha = 0.0f, hb = 0.0f;       // state rows r0, r0+1
    float xa = xg[((size_t)(b0 + r0)     * S_LEN) * HD + e];
    float xb = xg[((size_t)(b0 + r0 + 1) * S_LEN) * HD + e];

    ulonglong2 *mySlot = (g ? s23 : s01) + e;

    for (int s = 0; s < S_LEN; ++s) {
        // ---- staging: project h/x of own rows, norms stay in regs ----
        float hna, hnb, xna, xnb;
        float hpa = stage_proj(ha, hna);
        float hpb = stage_proj(hb, hnb);
        float xpa = stage_proj(xa, xna);
        float xpb = stage_proj(xb, xnb);
        ulonglong2 st;
        st.x = pack2f(hpa, xpa);
        st.y = pack2f(hpb, xpb);
        *mySlot = st;                  // one STS.128
        __syncthreads();

        // prefetch next inputs (hidden under matvec)
        if (s + 1 < S_LEN) {
            xa = xg[((size_t)(b0 + r0)     * S_LEN + (s + 1)) * HD + e];
            xb = xg[((size_t)(b0 + r0 + 1) * S_LEN + (s + 1)) * HD + e];
        }

        // ---- matvec over own k-range, all 4 rows, 4 independent chains ----
        unsigned long long pac0 = 0ull, pac1 = 0ull, pac2 = 0ull, pac3 = 0ull;
        const ulonglong2 *pA = s01 + g * KHALF;
        const ulonglong2 *pB = s23 + g * KHALF;
#pragma unroll
        for (int j = 0; j < KHALF; ++j) {
            ulonglong2 v01 = pA[j];    // {h0,x0,h1,x1} broadcast LDS.128
            ulonglong2 v23 = pB[j];
            pac0 = fma2(wu[j], v01.x, pac0);   // {w*h0, u*x0}
            pac1 = fma2(wu[j], v01.y, pac1);
            pac2 = fma2(wu[j], v23.x, pac2);
            pac3 = fma2(wu[j], v23.y, pac3);
        }
        // own rowpair partial stays local; other rowpair partial -> smem
        unsigned long long mineA, mineB;
        ulonglong2 theirs;
        if (g == 0) { mineA = pac0; mineB = pac1; theirs.x = pac2; theirs.y = pac3; }
        else        { mineA = pac2; mineB = pac3; theirs.x = pac0; theirs.y = pac1; }
        psum[g][e] = theirs;           // one STS.128
        __syncthreads();

        // ---- reduce: own partial + other group's partial for own rowpair ----
        ulonglong2 q = psum[1 - g][e]; // one LDS.128
        unsigned long long sA = add2(mineA, q.x);   // {wacc,uacc} row r0
        unsigned long long sB = add2(mineB, q.y);   // row r0+1
        float wA, uA, wB, uB;
        unpack2f(sA, wA, uA);
        unpack2f(sB, wB, uB);

        float oa = step_row(wA, hna, uA, xna, bia, bip);
        float ob = step_row(wB, hnb, uB, xnb, bia, bip);

        yg[((size_t)(b0 + r0)     * S_LEN + s) * HD + e] = oa;
        yg[((size_t)(b0 + r0 + 1) * S_LEN + s) * HD + e] = ob;
        ha = oa;
        hb = ob;
    }
}

extern "C" void kernel_launch(void *const *d_in, const int *in_sizes, int n_in,
                              void *d_out, int out_size) {
    const float *xg = (const float *)d_in[0];   // inputs [512,512,64,2]
    const float *wg = (const float *)d_in[1];   // w [64,2,64,2] -> [128,128]
    const float *ug = (const float *)d_in[2];   // u
    const float *bg = (const float *)d_in[3];   // b [64,2]
    float *yg = (float *)d_out;

    hyper_rnn_kernel<<<BATCH / NB, NTHR>>>(xg, wg, ug, bg, yg);
}